// round 15
// baseline (speedup 1.0000x reference)
#include <cuda_runtime.h>

#define HDIM 1024
#define BNUM 65536
#define NCOL 6                 // 2 joint + 4 group heads (g*2+c)
#define FOLD_BLOCKS 256
#define ROWS_PER_FOLD (HDIM / FOLD_BLOCKS)   // 4
#define NTILES (BNUM / 4)      // 16384 four-row tiles

typedef unsigned long long u64;

// Scratch (device globals — no allocation allowed)
__device__ float g_part[FOLD_BLOCKS][NCOL][HDIM];  // 6 MB partials
__device__ float g_M[NCOL * HDIM];                 // folded matrix, [j][h]
__device__ float g_bias[NCOL];
__device__ unsigned g_tile_ctr;                    // reset by fold_reduce each launch

__device__ __forceinline__ const float* col_wvec(int j, const float* W_joint, const float* W_groups) {
    return (j < 2) ? (W_joint + j * HDIM) : (W_groups + (j - 2) * HDIM);
}

// packed f32x2 FMA: acc(.lo,.hi) += a(.lo,.hi) * b(.lo,.hi)
__device__ __forceinline__ void ffma2(u64& acc, u64 a, u64 b) {
    asm("fma.rn.f32x2 %0, %1, %2, %0;" : "+l"(acc) : "l"(a), "l"(b));
}
__device__ __forceinline__ float unpack_sum(u64 a) {
    return __uint_as_float((unsigned)(a & 0xffffffffu)) + __uint_as_float((unsigned)(a >> 32));
}

// ---------------------------------------------------------------------------
// Fold stage 1: block k owns W_phi rows [4k, 4k+4) (coalesced full rows).
// ---------------------------------------------------------------------------
__global__ void __launch_bounds__(256) fold_part_kernel(const float* __restrict__ W_phi,
                                                        const float* __restrict__ W_groups,
                                                        const float* __restrict__ W_joint) {
    int t = threadIdx.x, k = blockIdx.x;
    int r0 = k * ROWS_PER_FOLD;
    int c0 = t * 4;

    float4 w[ROWS_PER_FOLD];
    #pragma unroll
    for (int r = 0; r < ROWS_PER_FOLD; r++)
        w[r] = *(const float4*)(W_phi + (size_t)(r0 + r) * HDIM + c0);

    float v[ROWS_PER_FOLD][NCOL];
    #pragma unroll
    for (int r = 0; r < ROWS_PER_FOLD; r++)
        #pragma unroll
        for (int j = 0; j < NCOL; j++)
            v[r][j] = __ldg(col_wvec(j, W_joint, W_groups) + r0 + r);

    float acc[NCOL][4];
    #pragma unroll
    for (int j = 0; j < NCOL; j++)
        acc[j][0] = acc[j][1] = acc[j][2] = acc[j][3] = 0.f;

    #pragma unroll
    for (int r = 0; r < ROWS_PER_FOLD; r++) {
        #pragma unroll
        for (int j = 0; j < NCOL; j++) {
            float s = v[r][j];
            acc[j][0] += s * w[r].x; acc[j][1] += s * w[r].y;
            acc[j][2] += s * w[r].z; acc[j][3] += s * w[r].w;
        }
    }
    #pragma unroll
    for (int j = 0; j < NCOL; j++)
        *(float4*)&g_part[k][j][c0] = make_float4(acc[j][0], acc[j][1], acc[j][2], acc[j][3]);
}

// ---------------------------------------------------------------------------
// Fold stage 2: blocks 0..95 reduce 256 partials (split-k by 4); block 96
// computes g_bias AND resets the main kernel's tile counter (stream order
// guarantees this completes before main starts -> graph-replay safe).
// ---------------------------------------------------------------------------
__global__ void __launch_bounds__(256) fold_reduce_kernel(const float* __restrict__ b_phi,
                                                          const float* __restrict__ W_groups,
                                                          const float* __restrict__ b_groups,
                                                          const float* __restrict__ W_joint,
                                                          const float* __restrict__ b_joint) {
    if (blockIdx.x == 96) {
        if (threadIdx.x == 192) g_tile_ctr = 0;
        int w = threadIdx.x >> 5, lane = threadIdx.x & 31;
        if (w >= NCOL) return;
        const float* wv = col_wvec(w, W_joint, W_groups);
        float s = 0.f;
        #pragma unroll 4
        for (int h = lane; h < HDIM; h += 32) s += b_phi[h] * wv[h];
        #pragma unroll
        for (int o = 16; o > 0; o >>= 1) s += __shfl_down_sync(0xffffffffu, s, o);
        if (lane == 0) g_bias[w] = s + ((w < 2) ? b_joint[w] : b_groups[w - 2]);
        return;
    }
    __shared__ float red[256];
    int t = threadIdx.x;
    int idx = blockIdx.x * 64 + (t & 63);     // 96*64 = 6144 outputs
    int qk  = t >> 6;
    const float* p = (const float*)g_part;
    float s = 0.f;
    #pragma unroll 8
    for (int k = 0; k < FOLD_BLOCKS / 4; k++)
        s += p[(size_t)(qk * (FOLD_BLOCKS / 4) + k) * NCOL * HDIM + idx];
    red[t] = s;
    __syncthreads();
    if (t < 64)
        g_M[blockIdx.x * 64 + t] = (red[t] + red[t + 64]) + (red[t + 128] + red[t + 192]);
}

// ---------------------------------------------------------------------------
// Main: persistent wave (444 blocks, 3/SM) with WARP-LEVEL DYNAMIC STEALING
// of 4-row tiles (16384 tiles). Fixes both the wave tail and between-SM
// speed spread. Lane (sub=lane>>3, q=lane&7): row tile*4+sub, h-slice
// i*32+q*4. Per chunk: 1 LDG.128 (4 lines/warp, perfectly coalesced),
// 6 LDS.128 (broadcast), 12 FFMA2. Pipeline depth 8 -> 4KB in flight/warp.
// ---------------------------------------------------------------------------
__global__ void __launch_bounds__(256, 3) main_kernel(const float* __restrict__ X,
                                                      const int* __restrict__ D,
                                                      const int* __restrict__ Dagn,
                                                      float* __restrict__ out) {
    __shared__ __align__(16) float sM[NCOL * HDIM];   // 24 KB, [j][h]
    __shared__ float sb[NCOL];
    int t = threadIdx.x;
    {
        const float4* src = (const float4*)g_M;
        float4* dst = (float4*)sM;
        #pragma unroll
        for (int i = 0; i < (NCOL * HDIM / 4) / 256; i++)
            dst[t + i * 256] = src[t + i * 256];
        if (t < NCOL) sb[t] = g_bias[t];
    }
    __syncthreads();

    int lane = t & 31;
    int sub = lane >> 3;          // row within tile
    int q   = lane & 7;           // 128B-column slot
    int q4  = q * 4;

    while (true) {
        unsigned tile;
        if (lane == 0) tile = atomicAdd(&g_tile_ctr, 1u);
        tile = __shfl_sync(0xffffffffu, tile, 0);
        if (tile >= NTILES) break;

        int row = (int)tile * 4 + sub;
        const float* xb = X + (size_t)row * HDIM + q4;

        u64 acc[NCOL];
        #pragma unroll
        for (int j = 0; j < NCOL; j++) acc[j] = 0ull;

        // depth-8 rolling pipeline (fully unrolled -> static reg indices)
        ulonglong2 b[8];
        #pragma unroll
        for (int k = 0; k < 8; k++)
            b[k] = __ldcs((const ulonglong2*)(xb + k * 32));

        #pragma unroll
        for (int i = 0; i < 32; i++) {
            ulonglong2 cur = b[i & 7];
            if (i + 8 < 32)
                b[i & 7] = __ldcs((const ulonglong2*)(xb + (i + 8) * 32));
            const float* mb = sM + i * 32 + q4;
            #pragma unroll
            for (int j = 0; j < NCOL; j++) {
                ulonglong2 m = *(const ulonglong2*)(mb + j * HDIM);   // 128B line, bcast
                ffma2(acc[j], cur.x, m.x);
                ffma2(acc[j], cur.y, m.y);
            }
        }

        // collapse packed halves, butterfly over q (lane bits 0..2)
        float a[NCOL];
        #pragma unroll
        for (int j = 0; j < NCOL; j++) {
            float s = unpack_sum(acc[j]);
            #pragma unroll
            for (int o = 1; o < 8; o <<= 1) s += __shfl_xor_sync(0xffffffffu, s, o);
            a[j] = s;
        }

        if (q == 0) {
            int d  = D[row];
            int da = Dagn[row];
            float j0  = a[0] + sb[0], j1  = a[1] + sb[1];
            float g00 = a[2] + sb[2], g01 = a[3] + sb[3];
            float g10 = a[4] + sb[4], g11 = a[5] + sb[5];
            *(float2*)(out + (size_t)row * 2) = make_float2(j0, j1);
            float2 gs = (d == 0)  ? make_float2(g00, g01) : make_float2(g10, g11);
            *(float2*)(out + (size_t)(BNUM + row) * 2) = gs;
            float2 ga = (da == 0) ? make_float2(g00, g01) : make_float2(g10, g11);
            *(float2*)(out + (size_t)(2 * BNUM + row) * 2) = ga;
        }
    }
}

// ---------------------------------------------------------------------------
extern "C" void kernel_launch(void* const* d_in, const int* in_sizes, int n_in,
                              void* d_out, int out_size) {
    const float* X        = (const float*)d_in[0];
    const float* W_phi    = (const float*)d_in[1];
    const float* b_phi    = (const float*)d_in[2];
    const float* W_groups = (const float*)d_in[3];
    const float* b_groups = (const float*)d_in[4];
    const float* W_joint  = (const float*)d_in[5];
    const float* b_joint  = (const float*)d_in[6];
    const int*   D        = (const int*)d_in[7];
    const int*   Dagn     = (const int*)d_in[8];
    float* out = (float*)d_out;

    fold_part_kernel<<<FOLD_BLOCKS, 256>>>(W_phi, W_groups, W_joint);
    fold_reduce_kernel<<<97, 256>>>(b_phi, W_groups, b_groups, W_joint, b_joint);
    main_kernel<<<444, 256>>>(X, D, Dagn, out);
}

// round 16
// speedup vs baseline: 1.2086x; 1.2086x over previous
#include <cuda_runtime.h>

#define HDIM 1024
#define BNUM 65536
#define NCOL 6                 // 2 joint + 4 group heads (g*2+c)
#define FOLD_BLOCKS 256
#define ROWS_PER_FOLD (HDIM / FOLD_BLOCKS)   // 4

typedef unsigned long long u64;

// Scratch (device globals — no allocation allowed)
__device__ float g_part[FOLD_BLOCKS][NCOL][HDIM];  // 6 MB partials
__device__ float g_M[NCOL * HDIM];                 // folded matrix, [j][h]
__device__ float g_bias[NCOL];
__device__ unsigned g_done_ctr;                    // partial-arrival counter
__device__ unsigned g_done2;                       // reducer-completion counter

__device__ __forceinline__ const float* col_wvec(int j, const float* W_joint, const float* W_groups) {
    return (j < 2) ? (W_joint + j * HDIM) : (W_groups + (j - 2) * HDIM);
}

// packed f32x2 FMA: acc(.lo,.hi) += a(.lo,.hi) * b(.lo,.hi)
__device__ __forceinline__ void ffma2(u64& acc, u64 a, u64 b) {
    asm("fma.rn.f32x2 %0, %1, %2, %0;" : "+l"(acc) : "l"(a), "l"(b));
}
__device__ __forceinline__ float unpack_sum(u64 a) {
    return __uint_as_float((unsigned)(a & 0xffffffffu)) + __uint_as_float((unsigned)(a >> 32));
}

// ---------------------------------------------------------------------------
// Merged fold: 256 blocks.
//   Phase 1 (all blocks): block k computes partial_k from W_phi rows [4k,4k+4).
//   Block 255 additionally computes g_bias (independent of partials).
//   Phase 2 (blocks 0..95): spin until all partials arrive, then reduce
//   (identical math/order to the old fold_reduce -> deterministic).
//   Counters self-reset after all reducers pass the spin (replay-safe).
// ---------------------------------------------------------------------------
__global__ void __launch_bounds__(256) fold_kernel(const float* __restrict__ W_phi,
                                                   const float* __restrict__ W_groups,
                                                   const float* __restrict__ W_joint,
                                                   const float* __restrict__ b_phi,
                                                   const float* __restrict__ b_groups,
                                                   const float* __restrict__ b_joint) {
    int t = threadIdx.x, k = blockIdx.x;

    // ---- Phase 1: partial (same as previous fold_part_kernel) ----
    {
        int r0 = k * ROWS_PER_FOLD;
        int c0 = t * 4;

        float4 w[ROWS_PER_FOLD];
        #pragma unroll
        for (int r = 0; r < ROWS_PER_FOLD; r++)
            w[r] = *(const float4*)(W_phi + (size_t)(r0 + r) * HDIM + c0);

        float v[ROWS_PER_FOLD][NCOL];
        #pragma unroll
        for (int r = 0; r < ROWS_PER_FOLD; r++)
            #pragma unroll
            for (int j = 0; j < NCOL; j++)
                v[r][j] = __ldg(col_wvec(j, W_joint, W_groups) + r0 + r);

        float acc[NCOL][4];
        #pragma unroll
        for (int j = 0; j < NCOL; j++)
            acc[j][0] = acc[j][1] = acc[j][2] = acc[j][3] = 0.f;

        #pragma unroll
        for (int r = 0; r < ROWS_PER_FOLD; r++) {
            #pragma unroll
            for (int j = 0; j < NCOL; j++) {
                float s = v[r][j];
                acc[j][0] += s * w[r].x; acc[j][1] += s * w[r].y;
                acc[j][2] += s * w[r].z; acc[j][3] += s * w[r].w;
            }
        }
        #pragma unroll
        for (int j = 0; j < NCOL; j++)
            *(float4*)&g_part[k][j][c0] = make_float4(acc[j][0], acc[j][1], acc[j][2], acc[j][3]);
    }

    __threadfence();          // make this thread's partial stores GPU-visible
    __syncthreads();          // all threads' fences done before the arrival signal
    if (t == 0) atomicAdd(&g_done_ctr, 1u);

    // ---- Bias (block 255; depends only on gmem inputs) ----
    if (k == 255 && t < 192) {
        int w = t >> 5, lane = t & 31;
        const float* wv = col_wvec(w, W_joint, W_groups);
        float s = 0.f;
        #pragma unroll 4
        for (int h = lane; h < HDIM; h += 32) s += b_phi[h] * wv[h];
        #pragma unroll
        for (int o = 16; o > 0; o >>= 1) s += __shfl_down_sync(0xffffffffu, s, o);
        if (lane == 0) g_bias[w] = s + ((w < 2) ? b_joint[w] : b_groups[w - 2]);
    }

    // ---- Phase 2: reduction (blocks 0..95 only; others exit) ----
    if (k < 96) {
        if (t == 0) {
            while (*(volatile unsigned*)&g_done_ctr < (unsigned)FOLD_BLOCKS) { }
        }
        __syncthreads();
        __threadfence();      // acquire: order partial reads after flag observation

        __shared__ float red[256];
        int idx = k * 64 + (t & 63);          // 96*64 = 6144 outputs
        int qk  = t >> 6;                     // split-k quarter: 64 partials each
        const float* p = (const float*)g_part;
        float s = 0.f;
        #pragma unroll 8
        for (int kk = 0; kk < FOLD_BLOCKS / 4; kk++)
            s += p[(size_t)(qk * (FOLD_BLOCKS / 4) + kk) * NCOL * HDIM + idx];
        red[t] = s;
        __syncthreads();
        if (t < 64)
            g_M[k * 64 + t] = (red[t] + red[t + 64]) + (red[t + 128] + red[t + 192]);

        // self-reset counters once ALL reducers have passed the spin
        __syncthreads();
        if (t == 0) {
            unsigned d2 = atomicAdd(&g_done2, 1u);
            if (d2 == 95u) { g_done_ctr = 0u; g_done2 = 0u; }
        }
    }
}

// ---------------------------------------------------------------------------
// Main: EXACT R12 structure (measured best). Warp-cooperative, barrier-free;
// packed f32x2 FMAs; 16 rows/warp; single u64 acc per (j,rr); prefetch
// distance 2 via fully-unrolled ping-pong; 2 blocks/SM.
// ---------------------------------------------------------------------------
__global__ void __launch_bounds__(256, 2) main_kernel(const float* __restrict__ X,
                                                      const int* __restrict__ D,
                                                      const int* __restrict__ Dagn,
                                                      float* __restrict__ out) {
    __shared__ __align__(16) float sM[NCOL * HDIM];   // 24 KB, [j][h]
    __shared__ float sb[NCOL];
    int t = threadIdx.x;
    {
        const float4* src = (const float4*)g_M;
        float4* dst = (float4*)sM;
        #pragma unroll
        for (int i = 0; i < (NCOL * HDIM / 4) / 256; i++)
            dst[t + i * 256] = src[t + i * 256];
        if (t < NCOL) sb[t] = g_bias[t];
    }
    __syncthreads();

    int lane = t & 31, w = t >> 5;
    int sub = lane >> 3;          // row within 4-row group
    int q   = lane & 7;           // 128B-column slot
    int q4  = q * 4;

    int R0 = blockIdx.x * 128 + w * 16;           // warp's 16 rows
    const float* xb = X + (size_t)(R0 + sub) * HDIM + q4;

    u64 acc[NCOL][4];             // 24 u64 = 48 regs
    #pragma unroll
    for (int j = 0; j < NCOL; j++)
        #pragma unroll
        for (int rr = 0; rr < 4; rr++)
            acc[j][rr] = 0ull;

    // ping-pong buffers, prefetch distance 2
    ulonglong2 b0[4], b1[4];
    #pragma unroll
    for (int rr = 0; rr < 4; rr++) {
        b0[rr] = __ldcs((const ulonglong2*)(xb + (size_t)(4 * rr) * HDIM + 0 * 32));
        b1[rr] = __ldcs((const ulonglong2*)(xb + (size_t)(4 * rr) * HDIM + 1 * 32));
    }

    #pragma unroll
    for (int ii = 0; ii < 16; ii++) {
        const int i = 2 * ii;
        ulonglong2 t0[4];
        if (i + 2 < 32) {
            #pragma unroll
            for (int rr = 0; rr < 4; rr++)
                t0[rr] = __ldcs((const ulonglong2*)(xb + (size_t)(4 * rr) * HDIM + (i + 2) * 32));
        }
        {
            const float* mb = sM + i * 32 + q4;
            #pragma unroll
            for (int j = 0; j < NCOL; j++) {
                ulonglong2 m = *(const ulonglong2*)(mb + j * HDIM);   // 128B line, bcast
                #pragma unroll
                for (int rr = 0; rr < 4; rr++) {
                    ffma2(acc[j][rr], b0[rr].x, m.x);
                    ffma2(acc[j][rr], b0[rr].y, m.y);
                }
            }
        }
        #pragma unroll
        for (int rr = 0; rr < 4; rr++) b0[rr] = t0[rr];

        ulonglong2 t1[4];
        if (i + 3 < 32) {
            #pragma unroll
            for (int rr = 0; rr < 4; rr++)
                t1[rr] = __ldcs((const ulonglong2*)(xb + (size_t)(4 * rr) * HDIM + (i + 3) * 32));
        }
        {
            const float* mb = sM + (i + 1) * 32 + q4;
            #pragma unroll
            for (int j = 0; j < NCOL; j++) {
                ulonglong2 m = *(const ulonglong2*)(mb + j * HDIM);
                #pragma unroll
                for (int rr = 0; rr < 4; rr++) {
                    ffma2(acc[j][rr], b1[rr].x, m.x);
                    ffma2(acc[j][rr], b1[rr].y, m.y);
                }
            }
        }
        #pragma unroll
        for (int rr = 0; rr < 4; rr++) b1[rr] = t1[rr];
    }

    // collapse packed halves, then butterfly over q (lane bits 0..2)
    float a[NCOL][4];
    #pragma unroll
    for (int j = 0; j < NCOL; j++)
        #pragma unroll
        for (int rr = 0; rr < 4; rr++) {
            float s = unpack_sum(acc[j][rr]);
            #pragma unroll
            for (int o = 1; o < 8; o <<= 1) s += __shfl_xor_sync(0xffffffffu, s, o);
            a[j][rr] = s;
        }

    if (q == 0) {
        #pragma unroll
        for (int rr = 0; rr < 4; rr++) {
            int row = R0 + sub + 4 * rr;
            int d  = D[row];
            int da = Dagn[row];
            float j0  = a[0][rr] + sb[0], j1  = a[1][rr] + sb[1];
            float g00 = a[2][rr] + sb[2], g01 = a[3][rr] + sb[3];
            float g10 = a[4][rr] + sb[4], g11 = a[5][rr] + sb[5];
            *(float2*)(out + (size_t)row * 2) = make_float2(j0, j1);
            float2 gs = (d == 0)  ? make_float2(g00, g01) : make_float2(g10, g11);
            *(float2*)(out + (size_t)(BNUM + row) * 2) = gs;
            float2 ga = (da == 0) ? make_float2(g00, g01) : make_float2(g10, g11);
            *(float2*)(out + (size_t)(2 * BNUM + row) * 2) = ga;
        }
    }
}

// ---------------------------------------------------------------------------
extern "C" void kernel_launch(void* const* d_in, const int* in_sizes, int n_in,
                              void* d_out, int out_size) {
    const float* X        = (const float*)d_in[0];
    const float* W_phi    = (const float*)d_in[1];
    const float* b_phi    = (const float*)d_in[2];
    const float* W_groups = (const float*)d_in[3];
    const float* b_groups = (const float*)d_in[4];
    const float* W_joint  = (const float*)d_in[5];
    const float* b_joint  = (const float*)d_in[6];
    const int*   D        = (const int*)d_in[7];
    const int*   Dagn     = (const int*)d_in[8];
    float* out = (float*)d_out;

    fold_kernel<<<FOLD_BLOCKS, 256>>>(W_phi, W_groups, W_joint, b_phi, b_groups, b_joint);
    main_kernel<<<BNUM / 128, 256>>>(X, D, Dagn, out);
}